// round 7
// baseline (speedup 1.0000x reference)
#include <cuda_runtime.h>
#include <math.h>

#define NB 64
#define NT 128
#define NN 64     // nodes
#define NC 128    // channels
#define NH 64     // hidden
#define NE 192    // 3 gates * 64
#define TP 68     // padded pitch for transposed 64-wide tiles
#define PM 34     // pitch for half-width (32) adjacency tiles

// Precomputed input-path gate contributions U[b,t,n,e] (biases included). 384 MiB.
static __device__ float g_U[(size_t)NB * NT * NN * NE];
// Pooled hidden means per (b,t), consumed by phase 3 decoder. 2 MiB.
static __device__ float g_pool[(size_t)NB * NT * NH];

__device__ __forceinline__ unsigned smem_u32(const void* p) {
    unsigned r;
    asm("{ .reg .u64 t; cvta.to.shared.u64 t, %1; cvt.u32.u64 %0, t; }" : "=r"(r) : "l"(p));
    return r;
}
__device__ __forceinline__ unsigned cluster_rank() {
    unsigned r; asm("mov.u32 %0, %%cluster_ctarank;" : "=r"(r)); return r;
}
__device__ __forceinline__ void st_peer_f2(unsigned laddr, unsigned peer, float a, float b) {
    unsigned raddr;
    asm volatile("mapa.shared::cluster.u32 %0, %1, %2;" : "=r"(raddr) : "r"(laddr), "r"(peer));
    asm volatile("st.shared::cluster.v2.f32 [%0], {%1, %2};" :: "r"(raddr), "f"(a), "f"(b) : "memory");
}
#define CLUSTER_SYNC() do { \
    asm volatile("barrier.cluster.arrive.aligned;" ::: "memory"); \
    asm volatile("barrier.cluster.wait.aligned;" ::: "memory"); } while (0)

__device__ __forceinline__ float rcp_ap(float x) {
    float y; asm("rcp.approx.f32 %0, %1;" : "=f"(y) : "f"(x)); return y;
}
__device__ __forceinline__ float tanh_fast(float x) {
    return 1.0f - 2.0f * rcp_ap(1.0f + __expf(2.0f * x));
}
__device__ __forceinline__ float sig_fast(float x) {
    return rcp_ap(1.0f + __expf(-x));
}

// ---------------------------------------------------------------------------
// Phase 1: per (b,t) tile. grid = 8192, block = 128, 3 CTAs/SM.
// Per-thread tile 8n x 4d. Weights/frames from gmem (L2-broadcast).
// smem = 69632 B.
// ---------------------------------------------------------------------------
// outT[d][n] = sum_m PT[d][m] * AT[m][n], 8n x 4d per thread (128 threads)
__device__ __forceinline__ void mmT64_128(float* __restrict__ outT,
                                          const float* __restrict__ PT,
                                          const float* __restrict__ AT,
                                          int n0, int d0)
{
    float acc[4][8];
#pragma unroll
    for (int i = 0; i < 4; i++)
#pragma unroll
        for (int j = 0; j < 8; j++) acc[i][j] = 0.f;

#pragma unroll 2
    for (int m = 0; m < 64; m++) {
        float4 a4a = *(const float4*)&AT[m * TP + n0];
        float4 a4b = *(const float4*)&AT[m * TP + n0 + 4];
        float av[8] = {a4a.x, a4a.y, a4a.z, a4a.w, a4b.x, a4b.y, a4b.z, a4b.w};
        float p[4];
#pragma unroll
        for (int i = 0; i < 4; i++) p[i] = PT[(d0 + i) * TP + m];
#pragma unroll
        for (int i = 0; i < 4; i++)
#pragma unroll
            for (int j = 0; j < 8; j++) acc[i][j] += p[i] * av[j];
    }
#pragma unroll
    for (int i = 0; i < 4; i++) {
        *(float4*)&outT[(d0 + i) * TP + n0] =
            make_float4(acc[i][0], acc[i][1], acc[i][2], acc[i][3]);
        *(float4*)&outT[(d0 + i) * TP + n0 + 4] =
            make_float4(acc[i][4], acc[i][5], acc[i][6], acc[i][7]);
    }
}

__global__ void __launch_bounds__(128, 3) phase1_kernel(
    const float* __restrict__ frames, const float* __restrict__ adj,
    const float* __restrict__ encW, const float* __restrict__ encB,
    const float* __restrict__ Wfu, const float* __restrict__ Wgu, const float* __restrict__ Wcu,
    const float* __restrict__ bf, const float* __restrict__ bg, const float* __restrict__ bc)
{
    extern __shared__ float sm[];
    float* sAT = sm;               // 4352
    float* sXT = sm + 4352;        // 4352
    float* sYT = sm + 8704;        // 4352
    float* sZT = sm + 13056;       // 4352

    const int tid = threadIdx.x;
    const int bt = blockIdx.x;
    const float* fr = frames + (size_t)bt * (NC * NN);
    const float* Ap = adj + (size_t)bt * (NN * NN);

    for (int i = tid; i < NN * NN; i += 128)
        sAT[(i & 63) * TP + (i >> 6)] = Ap[i];
    __syncthreads();

    const int n0 = (tid & 7) * 8;     // 8 n per thread
    const int d0 = (tid >> 3) * 4;    // 4 d per thread

    // Encode: xT[d][n] = sum_c encW[c][d] * fr[c][n] + encB[d]
    {
        float acc[4][8];
#pragma unroll
        for (int i = 0; i < 4; i++)
#pragma unroll
            for (int j = 0; j < 8; j++) acc[i][j] = 0.f;
#pragma unroll 2
        for (int c = 0; c < NC; c++) {
            float4 f4a = __ldg((const float4*)&fr[c * 64 + n0]);
            float4 f4b = __ldg((const float4*)&fr[c * 64 + n0 + 4]);
            float4 w4  = __ldg((const float4*)&encW[c * 64 + d0]);
            float fv[8] = {f4a.x, f4a.y, f4a.z, f4a.w, f4b.x, f4b.y, f4b.z, f4b.w};
            float wv[4] = {w4.x, w4.y, w4.z, w4.w};
#pragma unroll
            for (int i = 0; i < 4; i++)
#pragma unroll
                for (int j = 0; j < 8; j++) acc[i][j] += wv[i] * fv[j];
        }
        float4 b4 = __ldg((const float4*)&encB[d0]);
        float bv[4] = {b4.x, b4.y, b4.z, b4.w};
#pragma unroll
        for (int i = 0; i < 4; i++) {
            *(float4*)&sXT[(d0 + i) * TP + n0] =
                make_float4(acc[i][0] + bv[i], acc[i][1] + bv[i],
                            acc[i][2] + bv[i], acc[i][3] + bv[i]);
            *(float4*)&sXT[(d0 + i) * TP + n0 + 4] =
                make_float4(acc[i][4] + bv[i], acc[i][5] + bv[i],
                            acc[i][6] + bv[i], acc[i][7] + bv[i]);
        }
    }
    __syncthreads();
    mmT64_128(sYT, sXT, sAT, n0, d0);
    __syncthreads();
    mmT64_128(sZT, sYT, sAT, n0, d0);
    __syncthreads();

    // Gates: U = bias + sum_k y_k @ Wu_k   (weights streamed from gmem/L2)
    float accf[4][8], accg[4][8], accc[4][8];
    {
        float4 vf = __ldg((const float4*)&bf[d0]);
        float4 vg = __ldg((const float4*)&bg[d0]);
        float4 vc = __ldg((const float4*)&bc[d0]);
        float fv[4] = {vf.x, vf.y, vf.z, vf.w};
        float gv[4] = {vg.x, vg.y, vg.z, vg.w};
        float cv[4] = {vc.x, vc.y, vc.z, vc.w};
#pragma unroll
        for (int i = 0; i < 4; i++)
#pragma unroll
            for (int j = 0; j < 8; j++) {
                accf[i][j] = fv[i]; accg[i][j] = gv[i]; accc[i][j] = cv[i];
            }
    }
#pragma unroll 1
    for (int k = 0; k < 3; k++) {
        const float* src = (k == 0) ? sXT : ((k == 1) ? sYT : sZT);
        const float* Wf = Wfu + k * 4096;
        const float* Wg = Wgu + k * 4096;
        const float* Wc = Wcu + k * 4096;
#pragma unroll 2
        for (int m = 0; m < 64; m++) {
            float4 x4a = *(const float4*)&src[m * TP + n0];
            float4 x4b = *(const float4*)&src[m * TP + n0 + 4];
            float xv[8] = {x4a.x, x4a.y, x4a.z, x4a.w, x4b.x, x4b.y, x4b.z, x4b.w};
            float4 wf4 = __ldg((const float4*)&Wf[m * 64 + d0]);
            float4 wg4 = __ldg((const float4*)&Wg[m * 64 + d0]);
            float4 wc4 = __ldg((const float4*)&Wc[m * 64 + d0]);
            float wf[4] = {wf4.x, wf4.y, wf4.z, wf4.w};
            float wg[4] = {wg4.x, wg4.y, wg4.z, wg4.w};
            float wc[4] = {wc4.x, wc4.y, wc4.z, wc4.w};
#pragma unroll
            for (int i = 0; i < 4; i++)
#pragma unroll
                for (int j = 0; j < 8; j++) {
                    accf[i][j] += wf[i] * xv[j];
                    accg[i][j] += wg[i] * xv[j];
                    accc[i][j] += wc[i] * xv[j];
                }
        }
    }
    float* Ub = g_U + (size_t)bt * (NN * NE);
#pragma unroll
    for (int j = 0; j < 8; j++) {
        int row = (n0 + j) * NE;
        *(float4*)&Ub[row + d0]       = make_float4(accf[0][j], accf[1][j], accf[2][j], accf[3][j]);
        *(float4*)&Ub[row + 64 + d0]  = make_float4(accg[0][j], accg[1][j], accg[2][j], accg[3][j]);
        *(float4*)&Ub[row + 128 + d0] = make_float4(accc[0][j], accc[1][j], accc[2][j], accc[3][j]);
    }
}

// ---------------------------------------------------------------------------
// Phase 2: persistent recurrence, 2-CTA cluster per batch (n-split).
// grid = 128 (64 clusters), block = 512.
// ---------------------------------------------------------------------------
__device__ __forceinline__ void gate_hop512(float af[2][2], float ag[2][2], float ac[2][2],
                                            const float* __restrict__ xT,
                                            const float* __restrict__ wb,
                                            int ng0, int e0)
{
#pragma unroll 4
    for (int m = 0; m < 64; m++) {
        float2 x  = *(const float2*)&xT[m * TP + ng0];
        float2 f2 = *(const float2*)&wb[m * NE + e0];
        float2 g2 = *(const float2*)&wb[m * NE + 64 + e0];
        float2 c2 = *(const float2*)&wb[m * NE + 128 + e0];
        af[0][0] += f2.x * x.x;  af[0][1] += f2.x * x.y;
        af[1][0] += f2.y * x.x;  af[1][1] += f2.y * x.y;
        ag[0][0] += g2.x * x.x;  ag[0][1] += g2.x * x.y;
        ag[1][0] += g2.y * x.x;  ag[1][1] += g2.y * x.y;
        ac[0][0] += c2.x * x.x;  ac[0][1] += c2.x * x.y;
        ac[1][0] += c2.y * x.x;  ac[1][1] += c2.y * x.y;
    }
}

__device__ __forceinline__ void mm_half512(float acc[2][2],
                                           const float* __restrict__ PT,
                                           const float* __restrict__ AT,
                                           int d0, int nl0)
{
    acc[0][0] = acc[0][1] = acc[1][0] = acc[1][1] = 0.f;
#pragma unroll 4
    for (int m = 0; m < 64; m++) {
        float2 a2 = *(const float2*)&AT[m * PM + nl0];
        float p0 = PT[d0 * TP + m];
        float p1 = PT[(d0 + 1) * TP + m];
        acc[0][0] += p0 * a2.x;  acc[0][1] += p0 * a2.y;
        acc[1][0] += p1 * a2.x;  acc[1][1] += p1 * a2.y;
    }
}

__global__ void __launch_bounds__(512, 1) __cluster_dims__(2, 1, 1) phase2_kernel(
    const float* __restrict__ adj, const float* __restrict__ h0,
    const float* __restrict__ Wfh, const float* __restrict__ Wgh, const float* __restrict__ Wch,
    float* __restrict__ out)
{
    extern __shared__ float sm[];
    float* sWh  = sm;                 // 36864
    float* sAT  = sm + 36864;         // 2176 (own n-half)
    float* sHT  = sm + 39040;         // 4352 (full width)
    float* sH1T = sm + 43392;         // 4352 (full width, exchanged)
    float* sH2T = sm + 47744;         // 4352 (own half valid only)

    const int tid = threadIdx.x;
    const int b = blockIdx.x >> 1;
    const unsigned rank = cluster_rank();
    const unsigned peer = rank ^ 1u;
    const int halfbase = (int)rank * 32;

    for (int i = tid; i < 3 * 4096; i += 512) {
        int k = i >> 12; int r = i & 4095; int m = r >> 6; int e = r & 63;
        sWh[(k * 64 + m) * NE + e]       = Wfh[i];
        sWh[(k * 64 + m) * NE + 64 + e]  = Wgh[i];
        sWh[(k * 64 + m) * NE + 128 + e] = Wch[i];
    }
    for (int i = tid; i < 4096; i += 512)
        sHT[(i & 63) * TP + (i >> 6)] = h0[b * 4096 + i];
    __syncthreads();
    CLUSTER_SYNC();

    const unsigned u_sHT  = smem_u32(sHT);
    const unsigned u_sH1T = smem_u32(sH1T);

    const int nl0 = (tid & 15) * 2;        // local n (0..30)
    const int ng0 = halfbase + nl0;        // global n
    const int e0  = (tid >> 4) * 2;        // e/d tile base (0..62)

    for (int t = 0; t < NT; t++) {
        const float* Ap = adj + ((size_t)(b * NT + t)) * 4096 + (size_t)halfbase * 64;
        for (int i = tid; i < 2048; i += 512) {
            int nl = i >> 6, m = i & 63;
            sAT[m * PM + nl] = Ap[nl * 64 + m];
        }
        float af[2][2], ag[2][2], ac[2][2];
        {
            const float* Ub = g_U + ((size_t)(b * NT + t)) * (NN * NE);
#pragma unroll
            for (int j = 0; j < 2; j++) {
                int row = (ng0 + j) * NE;
                float2 uf = *(const float2*)&Ub[row + e0];
                float2 ug = *(const float2*)&Ub[row + 64 + e0];
                float2 uc = *(const float2*)&Ub[row + 128 + e0];
                af[0][j] = uf.x; af[1][j] = uf.y;
                ag[0][j] = ug.x; ag[1][j] = ug.y;
                ac[0][j] = uc.x; ac[1][j] = uc.y;
            }
        }
        __syncthreads();

        // hop 0 (x = h) + h1 = A h (own rows)
        gate_hop512(af, ag, ac, sHT, sWh, ng0, e0);
        float mmv[2][2];
        mm_half512(mmv, sHT, sAT, e0, nl0);
#pragma unroll
        for (int i = 0; i < 2; i++) {
            int off = (e0 + i) * TP + ng0;
            *(float2*)&sH1T[off] = make_float2(mmv[i][0], mmv[i][1]);
            st_peer_f2(u_sH1T + (unsigned)off * 4u, peer, mmv[i][0], mmv[i][1]);
        }
        CLUSTER_SYNC();   // h1 full everywhere

        // hop 1 (x = h1) + h2 = A h1 (own rows, local only)
        gate_hop512(af, ag, ac, sH1T, sWh + 64 * NE, ng0, e0);
        mm_half512(mmv, sH1T, sAT, e0, nl0);
#pragma unroll
        for (int i = 0; i < 2; i++)
            *(float2*)&sH2T[(e0 + i) * TP + ng0] = make_float2(mmv[i][0], mmv[i][1]);
        __syncthreads();

        // hop 2 (x = h2)
        gate_hop512(af, ag, ac, sH2T, sWh + 128 * NE, ng0, e0);

        // Nonlinearity -> h_new own tile; write local + peer
#pragma unroll
        for (int i = 0; i < 2; i++) {
            float hv0, hv1;
            {
                float f = sig_fast(af[i][0]);
                float tg = tanh_fast(ag[i][0]);
                float tc = tanh_fast(ac[i][0]);
                hv0 = f * (tg - tc) + tc;
            }
            {
                float f = sig_fast(af[i][1]);
                float tg = tanh_fast(ag[i][1]);
                float tc = tanh_fast(ac[i][1]);
                hv1 = f * (tg - tc) + tc;
            }
            int off = (e0 + i) * TP + ng0;
            *(float2*)&sHT[off] = make_float2(hv0, hv1);
            st_peer_f2(u_sHT + (unsigned)off * 4u, peer, hv0, hv1);
        }
        CLUSTER_SYNC();   // h_new full everywhere

        // Pooled mean (rank 0): pooled[d] = mean_n sHT[d][n]
        if (rank == 0) {
            int d = tid >> 3, q = tid & 7;
            float s = 0.f;
            const float* row = &sHT[d * TP + q * 8];
#pragma unroll
            for (int nn = 0; nn < 8; nn++) s += row[nn];
            s += __shfl_xor_sync(0xFFFFFFFFu, s, 1);
            s += __shfl_xor_sync(0xFFFFFFFFu, s, 2);
            s += __shfl_xor_sync(0xFFFFFFFFu, s, 4);
            if (q == 0)
                g_pool[((size_t)(b * NT + t)) * NH + d] = s * (1.0f / 64.0f);
        }
        __syncthreads();
    }

    if (rank == 0) {
        float* fh = out + (size_t)NB * NT * 6 + (size_t)b * (NN * NH);
        for (int i = tid; i < 4096; i += 512)
            fh[i] = sHT[(i & 63) * TP + (i >> 6)];
    }
    CLUSTER_SYNC();   // no CTA exits while peer may still target its smem
}

// ---------------------------------------------------------------------------
// Phase 3: decoder MLP per (b,t). grid = 8192, block = 128.
// ---------------------------------------------------------------------------
__global__ void __launch_bounds__(128, 8) phase3_kernel(
    const float* __restrict__ dW1, const float* __restrict__ db1,
    const float* __restrict__ dW2, const float* __restrict__ db2,
    const float* __restrict__ dW3, const float* __restrict__ db3,
    const float* __restrict__ osc, const float* __restrict__ obi,
    float* __restrict__ out)
{
    __shared__ float sp[64];
    __shared__ float z1[128];
    __shared__ float z2[64];
    const int bt = blockIdx.x;
    const int tid = threadIdx.x;

    if (tid < 64) sp[tid] = g_pool[(size_t)bt * NH + tid];
    __syncthreads();
    {
        float a = db1[tid];
#pragma unroll 4
        for (int d = 0; d < 64; d++) a += sp[d] * dW1[d * 128 + tid];
        z1[tid] = fmaxf(a, 0.f);
    }
    __syncthreads();
    if (tid < 64) {
        float a = db2[tid];
#pragma unroll 4
        for (int i = 0; i < 128; i++) a += z1[i] * dW2[i * 64 + tid];
        z2[tid] = fmaxf(a, 0.f);
    }
    __syncthreads();
    if (tid < 6) {
        float a = db3[tid];
#pragma unroll 4
        for (int j = 0; j < 64; j++) a += z2[j] * dW3[j * 6 + tid];
        out[(size_t)bt * 6 + tid] = a * osc[tid] + obi[tid];
    }
}

extern "C" void kernel_launch(void* const* d_in, const int* in_sizes, int n_in,
                              void* d_out, int out_size) {
    const float* frames = (const float*)d_in[0];
    const float* adj    = (const float*)d_in[1];
    const float* h0     = (const float*)d_in[2];
    const float* encW   = (const float*)d_in[3];
    const float* encB   = (const float*)d_in[4];
    const float* Wfh    = (const float*)d_in[5];
    const float* Wfu    = (const float*)d_in[6];
    const float* bf     = (const float*)d_in[7];
    const float* Wgh    = (const float*)d_in[8];
    const float* Wgu    = (const float*)d_in[9];
    const float* bg     = (const float*)d_in[10];
    const float* Wch    = (const float*)d_in[11];
    const float* Wcu    = (const float*)d_in[12];
    const float* bc     = (const float*)d_in[13];
    const float* dW1    = (const float*)d_in[14];
    const float* db1    = (const float*)d_in[15];
    const float* dW2    = (const float*)d_in[16];
    const float* db2    = (const float*)d_in[17];
    const float* dW3    = (const float*)d_in[18];
    const float* db3    = (const float*)d_in[19];
    const float* osc    = (const float*)d_in[20];
    const float* obi    = (const float*)d_in[21];
    float* out = (float*)d_out;

    const int smem1 = 17408 * 4;   // 69632 B  -> 3 CTAs/SM
    const int smem2 = 52096 * 4;   // 208384 B
    cudaFuncSetAttribute(phase1_kernel, cudaFuncAttributeMaxDynamicSharedMemorySize, smem1);
    cudaFuncSetAttribute(phase2_kernel, cudaFuncAttributeMaxDynamicSharedMemorySize, smem2);

    phase1_kernel<<<NB * NT, 128, smem1>>>(frames, adj, encW, encB,
                                           Wfu, Wgu, Wcu, bf, bg, bc);
    phase2_kernel<<<NB * 2, 512, smem2>>>(adj, h0, Wfh, Wgh, Wch, out);
    phase3_kernel<<<NB * NT, 128>>>(dW1, db1, dW2, db2, dW3, db3, osc, obi, out);
}

// round 9
// speedup vs baseline: 1.0507x; 1.0507x over previous
#include <cuda_runtime.h>
#include <math.h>

#define NB 64
#define NT 128
#define NN 64     // nodes
#define NC 128    // channels
#define NH 64     // hidden
#define NE 192    // 3 gates * 64
#define TP 68     // padded pitch for transposed 64-wide tiles
#define PM 34     // pitch for half-width (32) adjacency tiles

// Precomputed input-path gate contributions U[b,t,n,e] (biases included). 384 MiB.
static __device__ float g_U[(size_t)NB * NT * NN * NE];
// Pooled hidden means per (b,t), consumed by phase 3 decoder. 2 MiB.
static __device__ float g_pool[(size_t)NB * NT * NH];

__device__ __forceinline__ unsigned smem_u32(const void* p) {
    unsigned r;
    asm("{ .reg .u64 t; cvta.to.shared.u64 t, %1; cvt.u32.u64 %0, t; }" : "=r"(r) : "l"(p));
    return r;
}
__device__ __forceinline__ unsigned cluster_rank() {
    unsigned r; asm("mov.u32 %0, %%cluster_ctarank;" : "=r"(r)); return r;
}
__device__ __forceinline__ void st_peer_f2(unsigned laddr, unsigned peer, float a, float b) {
    unsigned raddr;
    asm volatile("mapa.shared::cluster.u32 %0, %1, %2;" : "=r"(raddr) : "r"(laddr), "r"(peer));
    asm volatile("st.shared::cluster.v2.f32 [%0], {%1, %2};" :: "r"(raddr), "f"(a), "f"(b) : "memory");
}
#define CLUSTER_ARRIVE() asm volatile("barrier.cluster.arrive.aligned;" ::: "memory")
#define CLUSTER_WAIT()   asm volatile("barrier.cluster.wait.aligned;" ::: "memory")
#define CLUSTER_SYNC() do { CLUSTER_ARRIVE(); CLUSTER_WAIT(); } while (0)

__device__ __forceinline__ float rcp_ap(float x) {
    float y; asm("rcp.approx.f32 %0, %1;" : "=f"(y) : "f"(x)); return y;
}
__device__ __forceinline__ float tanh_fast(float x) {
    return 1.0f - 2.0f * rcp_ap(1.0f + __expf(2.0f * x));
}
__device__ __forceinline__ float sig_fast(float x) {
    return rcp_ap(1.0f + __expf(-x));
}

// ---------------------------------------------------------------------------
// Phase 1: per (b,t) tile. grid = 8192, block = 256, 2 CTAs/SM. (R6 config)
// ---------------------------------------------------------------------------
__device__ __forceinline__ void mmT64(float* __restrict__ outT,
                                      const float* __restrict__ PT,
                                      const float* __restrict__ AT,
                                      int tid)
{
    const int n0 = (tid & 15) * 4;
    const int d0 = (tid >> 4) * 4;
    float acc[4][4];
#pragma unroll
    for (int i = 0; i < 4; i++)
#pragma unroll
        for (int j = 0; j < 4; j++) acc[i][j] = 0.f;

#pragma unroll 4
    for (int m = 0; m < 64; m++) {
        float4 a4 = *(const float4*)&AT[m * TP + n0];
        float av[4] = {a4.x, a4.y, a4.z, a4.w};
        float p[4];
#pragma unroll
        for (int i = 0; i < 4; i++) p[i] = PT[(d0 + i) * TP + m];
#pragma unroll
        for (int i = 0; i < 4; i++)
#pragma unroll
            for (int j = 0; j < 4; j++) acc[i][j] += p[i] * av[j];
    }
#pragma unroll
    for (int i = 0; i < 4; i++)
        *(float4*)&outT[(d0 + i) * TP + n0] =
            make_float4(acc[i][0], acc[i][1], acc[i][2], acc[i][3]);
}

__global__ void __launch_bounds__(256, 2) phase1_kernel(
    const float* __restrict__ frames, const float* __restrict__ adj,
    const float* __restrict__ encW, const float* __restrict__ encB,
    const float* __restrict__ Wfu, const float* __restrict__ Wgu, const float* __restrict__ Wcu,
    const float* __restrict__ bf, const float* __restrict__ bg, const float* __restrict__ bc)
{
    extern __shared__ float sm[];
    float* sAT = sm;               // 4352
    float* sXT = sm + 4352;        // 4352
    float* sYT = sm + 8704;        // 4352
    float* sZT = sm + 13056;       // 4352

    const int tid = threadIdx.x;
    const int bt = blockIdx.x;
    const float* fr = frames + (size_t)bt * (NC * NN);
    const float* Ap = adj + (size_t)bt * (NN * NN);

    for (int i = tid; i < NN * NN; i += 256)
        sAT[(i & 63) * TP + (i >> 6)] = Ap[i];
    __syncthreads();

    const int n0 = (tid & 15) * 4;
    const int d0 = (tid >> 4) * 4;

    // Encode: xT[d][n] = sum_c encW[c][d] * fr[c][n] + encB[d]
    {
        float acc[4][4];
#pragma unroll
        for (int i = 0; i < 4; i++)
#pragma unroll
            for (int j = 0; j < 4; j++) acc[i][j] = 0.f;
#pragma unroll 4
        for (int c = 0; c < NC; c++) {
            float4 a4 = __ldg((const float4*)&fr[c * 64 + n0]);
            float4 w4 = __ldg((const float4*)&encW[c * 64 + d0]);
            float av[4] = {a4.x, a4.y, a4.z, a4.w};
            float wv[4] = {w4.x, w4.y, w4.z, w4.w};
#pragma unroll
            for (int i = 0; i < 4; i++)
#pragma unroll
                for (int j = 0; j < 4; j++) acc[i][j] += wv[i] * av[j];
        }
        float4 b4 = __ldg((const float4*)&encB[d0]);
        float bv[4] = {b4.x, b4.y, b4.z, b4.w};
#pragma unroll
        for (int i = 0; i < 4; i++)
            *(float4*)&sXT[(d0 + i) * TP + n0] =
                make_float4(acc[i][0] + bv[i], acc[i][1] + bv[i],
                            acc[i][2] + bv[i], acc[i][3] + bv[i]);
    }
    __syncthreads();
    mmT64(sYT, sXT, sAT, tid);
    __syncthreads();
    mmT64(sZT, sYT, sAT, tid);
    __syncthreads();

    float accf[4][4], accg[4][4], accc[4][4];
    {
        float4 vf = __ldg((const float4*)&bf[d0]);
        float4 vg = __ldg((const float4*)&bg[d0]);
        float4 vc = __ldg((const float4*)&bc[d0]);
        float fv[4] = {vf.x, vf.y, vf.z, vf.w};
        float gv[4] = {vg.x, vg.y, vg.z, vg.w};
        float cv[4] = {vc.x, vc.y, vc.z, vc.w};
#pragma unroll
        for (int i = 0; i < 4; i++)
#pragma unroll
            for (int j = 0; j < 4; j++) {
                accf[i][j] = fv[i]; accg[i][j] = gv[i]; accc[i][j] = cv[i];
            }
    }
#pragma unroll 1
    for (int k = 0; k < 3; k++) {
        const float* src = (k == 0) ? sXT : ((k == 1) ? sYT : sZT);
        const float* Wf = Wfu + k * 4096;
        const float* Wg = Wgu + k * 4096;
        const float* Wc = Wcu + k * 4096;
#pragma unroll 4
        for (int m = 0; m < 64; m++) {
            float4 x4 = *(const float4*)&src[m * TP + n0];
            float xv[4] = {x4.x, x4.y, x4.z, x4.w};
            float4 wf4 = __ldg((const float4*)&Wf[m * 64 + d0]);
            float4 wg4 = __ldg((const float4*)&Wg[m * 64 + d0]);
            float4 wc4 = __ldg((const float4*)&Wc[m * 64 + d0]);
            float wf[4] = {wf4.x, wf4.y, wf4.z, wf4.w};
            float wg[4] = {wg4.x, wg4.y, wg4.z, wg4.w};
            float wc[4] = {wc4.x, wc4.y, wc4.z, wc4.w};
#pragma unroll
            for (int i = 0; i < 4; i++)
#pragma unroll
                for (int j = 0; j < 4; j++) {
                    accf[i][j] += wf[i] * xv[j];
                    accg[i][j] += wg[i] * xv[j];
                    accc[i][j] += wc[i] * xv[j];
                }
        }
    }
    float* Ub = g_U + (size_t)bt * (NN * NE);
#pragma unroll
    for (int j = 0; j < 4; j++) {
        int row = (n0 + j) * NE;
        *(float4*)&Ub[row + d0]       = make_float4(accf[0][j], accf[1][j], accf[2][j], accf[3][j]);
        *(float4*)&Ub[row + 64 + d0]  = make_float4(accg[0][j], accg[1][j], accg[2][j], accg[3][j]);
        *(float4*)&Ub[row + 128 + d0] = make_float4(accc[0][j], accc[1][j], accc[2][j], accc[3][j]);
    }
}

// ---------------------------------------------------------------------------
// Phase 2: persistent recurrence, 2-CTA cluster per batch (n-split),
// split arrive/wait + U prefetch, WITH the intra-CTA syncs restored.
// grid = 128 (64 clusters), block = 512.
// ---------------------------------------------------------------------------
__device__ __forceinline__ void gate_hop512(float af[2][2], float ag[2][2], float ac[2][2],
                                            const float* __restrict__ xT,
                                            const float* __restrict__ wb,
                                            int ng0, int e0)
{
#pragma unroll 4
    for (int m = 0; m < 64; m++) {
        float2 x  = *(const float2*)&xT[m * TP + ng0];
        float2 f2 = *(const float2*)&wb[m * NE + e0];
        float2 g2 = *(const float2*)&wb[m * NE + 64 + e0];
        float2 c2 = *(const float2*)&wb[m * NE + 128 + e0];
        af[0][0] += f2.x * x.x;  af[0][1] += f2.x * x.y;
        af[1][0] += f2.y * x.x;  af[1][1] += f2.y * x.y;
        ag[0][0] += g2.x * x.x;  ag[0][1] += g2.x * x.y;
        ag[1][0] += g2.y * x.x;  ag[1][1] += g2.y * x.y;
        ac[0][0] += c2.x * x.x;  ac[0][1] += c2.x * x.y;
        ac[1][0] += c2.y * x.x;  ac[1][1] += c2.y * x.y;
    }
}

__device__ __forceinline__ void mm_half512(float acc[2][2],
                                           const float* __restrict__ PT,
                                           const float* __restrict__ AT,
                                           int d0, int nl0)
{
    acc[0][0] = acc[0][1] = acc[1][0] = acc[1][1] = 0.f;
#pragma unroll 4
    for (int m = 0; m < 64; m++) {
        float2 a2 = *(const float2*)&AT[m * PM + nl0];
        float p0 = PT[d0 * TP + m];
        float p1 = PT[(d0 + 1) * TP + m];
        acc[0][0] += p0 * a2.x;  acc[0][1] += p0 * a2.y;
        acc[1][0] += p1 * a2.x;  acc[1][1] += p1 * a2.y;
    }
}

__global__ void __launch_bounds__(512, 1) __cluster_dims__(2, 1, 1) phase2_kernel(
    const float* __restrict__ adj, const float* __restrict__ h0,
    const float* __restrict__ Wfh, const float* __restrict__ Wgh, const float* __restrict__ Wch,
    float* __restrict__ out)
{
    extern __shared__ float sm[];
    float* sWh  = sm;                 // 36864
    float* sAT  = sm + 36864;         // 2176 (own n-half)
    float* sHT  = sm + 39040;         // 4352 (full width)
    float* sH1T = sm + 43392;         // 4352 (full width, exchanged)
    float* sH2T = sm + 47744;         // 4352 (own half valid only)

    const int tid = threadIdx.x;
    const int b = blockIdx.x >> 1;
    const unsigned rank = cluster_rank();
    const unsigned peer = rank ^ 1u;
    const int halfbase = (int)rank * 32;

    for (int i = tid; i < 3 * 4096; i += 512) {
        int k = i >> 12; int r = i & 4095; int m = r >> 6; int e = r & 63;
        sWh[(k * 64 + m) * NE + e]       = Wfh[i];
        sWh[(k * 64 + m) * NE + 64 + e]  = Wgh[i];
        sWh[(k * 64 + m) * NE + 128 + e] = Wch[i];
    }
    for (int i = tid; i < 4096; i += 512)
        sHT[(i & 63) * TP + (i >> 6)] = h0[b * 4096 + i];
    __syncthreads();
    CLUSTER_SYNC();
    CLUSTER_ARRIVE();   // pre-arm: loop starts with WAIT

    const unsigned u_sHT  = smem_u32(sHT);
    const unsigned u_sH1T = smem_u32(sH1T);

    const int nl0 = (tid & 15) * 2;        // local n (0..30)
    const int ng0 = halfbase + nl0;        // global n
    const int e0  = (tid >> 4) * 2;        // e/d tile base (0..62)

    // U prefetch registers (step 0 preload)
    float2 puf[2], pug[2], puc[2];
    {
        const float* Ub = g_U + ((size_t)(b * NT)) * (NN * NE);
#pragma unroll
        for (int j = 0; j < 2; j++) {
            int row = (ng0 + j) * NE;
            puf[j] = *(const float2*)&Ub[row + e0];
            pug[j] = *(const float2*)&Ub[row + 64 + e0];
            puc[j] = *(const float2*)&Ub[row + 128 + e0];
        }
    }

    for (int t = 0; t < NT; t++) {
        // Init gate accs from prefetched U
        float af[2][2], ag[2][2], ac[2][2];
#pragma unroll
        for (int j = 0; j < 2; j++) {
            af[0][j] = puf[j].x; af[1][j] = puf[j].y;
            ag[0][j] = pug[j].x; ag[1][j] = pug[j].y;
            ac[0][j] = puc[j].x; ac[1][j] = puc[j].y;
        }
        // Issue U(t+1) prefetch (clamped; consumed next iteration)
        {
            int btn = b * NT + t + 1;
            if (btn > NB * NT - 1) btn = NB * NT - 1;
            const float* Ub = g_U + (size_t)btn * (NN * NE);
#pragma unroll
            for (int j = 0; j < 2; j++) {
                int row = (ng0 + j) * NE;
                puf[j] = *(const float2*)&Ub[row + e0];
                pug[j] = *(const float2*)&Ub[row + 64 + e0];
                puc[j] = *(const float2*)&Ub[row + 128 + e0];
            }
        }
        // Stage own-half adjacency (first consumed at mm1, after the post-WAIT sync)
        const float* Ap = adj + ((size_t)(b * NT + t)) * 4096 + (size_t)halfbase * 64;
        for (int i = tid; i < 2048; i += 512) {
            int nl = i >> 6, m = i & 63;
            sAT[m * PM + nl] = Ap[nl * 64 + m];
        }

        // hop 0: gates over x = h (own n columns — local, written before loop-end sync)
        gate_hop512(af, ag, ac, sHT, sWh, ng0, e0);

        CLUSTER_WAIT();    // full h(t) visible (peer h_new push of step t-1)
        __syncthreads();   // intra-CTA: sAT staging complete before mm1

        // pool of h(t-1) (full sHT; not yet overwritten this step)
        if (rank == 0 && t > 0) {
            int d = tid >> 3, q = tid & 7;
            float s = 0.f;
            const float* row = &sHT[d * TP + q * 8];
#pragma unroll
            for (int nn = 0; nn < 8; nn++) s += row[nn];
            s += __shfl_xor_sync(0xFFFFFFFFu, s, 1);
            s += __shfl_xor_sync(0xFFFFFFFFu, s, 2);
            s += __shfl_xor_sync(0xFFFFFFFFu, s, 4);
            if (q == 0)
                g_pool[((size_t)(b * NT + t - 1)) * NH + d] = s * (1.0f / 64.0f);
        }

        // mm1: h1 = A h (own rows); write local + push peer; arrive
        float mmv[2][2];
        mm_half512(mmv, sHT, sAT, e0, nl0);
#pragma unroll
        for (int i = 0; i < 2; i++) {
            int off = (e0 + i) * TP + ng0;
            *(float2*)&sH1T[off] = make_float2(mmv[i][0], mmv[i][1]);
            st_peer_f2(u_sH1T + (unsigned)off * 4u, peer, mmv[i][0], mmv[i][1]);
        }
        CLUSTER_ARRIVE();
        __syncthreads();   // intra-CTA: local sH1T writes visible before hop1 reads

        // hop 1: gates over x = h1 (own n columns — local)
        gate_hop512(af, ag, ac, sH1T, sWh + 64 * NE, ng0, e0);

        CLUSTER_WAIT();    // full h1 visible

        // mm2: h2 = A h1 (own rows, local only)
        mm_half512(mmv, sH1T, sAT, e0, nl0);
#pragma unroll
        for (int i = 0; i < 2; i++)
            *(float2*)&sH2T[(e0 + i) * TP + ng0] = make_float2(mmv[i][0], mmv[i][1]);
        __syncthreads();   // sH2T complete before hop2

        // hop 2: gates over x = h2 (own half)
        gate_hop512(af, ag, ac, sH2T, sWh + 128 * NE, ng0, e0);

        // Nonlinearity -> h_new own tile; write local + push peer; arrive
#pragma unroll
        for (int i = 0; i < 2; i++) {
            float hv0, hv1;
            {
                float f = sig_fast(af[i][0]);
                float tg = tanh_fast(ag[i][0]);
                float tc = tanh_fast(ac[i][0]);
                hv0 = f * (tg - tc) + tc;
            }
            {
                float f = sig_fast(af[i][1]);
                float tg = tanh_fast(ag[i][1]);
                float tc = tanh_fast(ac[i][1]);
                hv1 = f * (tg - tc) + tc;
            }
            int off = (e0 + i) * TP + ng0;
            *(float2*)&sHT[off] = make_float2(hv0, hv1);
            st_peer_f2(u_sHT + (unsigned)off * 4u, peer, hv0, hv1);
        }
        CLUSTER_ARRIVE();
        __syncthreads();   // own-col h_new + sAT reuse protected for next iter
    }

    CLUSTER_WAIT();   // final h full everywhere

    if (rank == 0) {
        // pool of h(127)
        {
            int d = tid >> 3, q = tid & 7;
            float s = 0.f;
            const float* row = &sHT[d * TP + q * 8];
#pragma unroll
            for (int nn = 0; nn < 8; nn++) s += row[nn];
            s += __shfl_xor_sync(0xFFFFFFFFu, s, 1);
            s += __shfl_xor_sync(0xFFFFFFFFu, s, 2);
            s += __shfl_xor_sync(0xFFFFFFFFu, s, 4);
            if (q == 0)
                g_pool[((size_t)(b * NT + NT - 1)) * NH + d] = s * (1.0f / 64.0f);
        }
        float* fh = out + (size_t)NB * NT * 6 + (size_t)b * (NN * NH);
        for (int i = tid; i < 4096; i += 512)
            fh[i] = sHT[(i & 63) * TP + (i >> 6)];
    }
}

// ---------------------------------------------------------------------------
// Phase 3: decoder MLP per (b,t). grid = 8192, block = 128.
// ---------------------------------------------------------------------------
__global__ void __launch_bounds__(128, 8) phase3_kernel(
    const float* __restrict__ dW1, const float* __restrict__ db1,
    const float* __restrict__ dW2, const float* __restrict__ db2,
    const float* __restrict__ dW3, const float* __restrict__ db3,
    const float* __restrict__ osc, const float* __restrict__ obi,
    float* __restrict__ out)
{
    __shared__ float sp[64];
    __shared__ float z1[128];
    __shared__ float z2[64];
    const int bt = blockIdx.x;
    const int tid = threadIdx.x;

    if (tid < 64) sp[tid] = g_pool[(size_t)bt * NH + tid];
    __syncthreads();
    {
        float a = db1[tid];
#pragma unroll 4
        for (int d = 0; d < 64; d++) a += sp[d] * dW1[d * 128 + tid];
        z1[tid] = fmaxf(a, 0.f);
    }
    __syncthreads();
    if (tid < 64) {
        float a = db2[tid];
#pragma unroll 4
        for (int i = 0; i < 128; i++) a += z1[i] * dW2[i * 64 + tid];
        z2[tid] = fmaxf(a, 0.f);
    }
    __syncthreads();
    if (tid < 6) {
        float a = db3[tid];
#pragma unroll 4
        for (int j = 0; j < 64; j++) a += z2[j] * dW3[j * 6 + tid];
        out[(size_t)bt * 6 + tid] = a * osc[tid] + obi[tid];
    }
}

extern "C" void kernel_launch(void* const* d_in, const int* in_sizes, int n_in,
                              void* d_out, int out_size) {
    const float* frames = (const float*)d_in[0];
    const float* adj    = (const float*)d_in[1];
    const float* h0     = (const float*)d_in[2];
    const float* encW   = (const float*)d_in[3];
    const float* encB   = (const float*)d_in[4];
    const float* Wfh    = (const float*)d_in[5];
    const float* Wfu    = (const float*)d_in[6];
    const float* bf     = (const float*)d_in[7];
    const float* Wgh    = (const float*)d_in[8];
    const float* Wgu    = (const float*)d_in[9];
    const float* bg     = (const float*)d_in[10];
    const float* Wch    = (const float*)d_in[11];
    const float* Wcu    = (const float*)d_in[12];
    const float* bc     = (const float*)d_in[13];
    const float* dW1    = (const float*)d_in[14];
    const float* db1    = (const float*)d_in[15];
    const float* dW2    = (const float*)d_in[16];
    const float* db2    = (const float*)d_in[17];
    const float* dW3    = (const float*)d_in[18];
    const float* db3    = (const float*)d_in[19];
    const float* osc    = (const float*)d_in[20];
    const float* obi    = (const float*)d_in[21];
    float* out = (float*)d_out;

    const int smem1 = 17408 * 4;   // 69632 B  -> 2 CTAs/SM
    const int smem2 = 52096 * 4;   // 208384 B
    cudaFuncSetAttribute(phase1_kernel, cudaFuncAttributeMaxDynamicSharedMemorySize, smem1);
    cudaFuncSetAttribute(phase2_kernel, cudaFuncAttributeMaxDynamicSharedMemorySize, smem2);

    phase1_kernel<<<NB * NT, 256, smem1>>>(frames, adj, encW, encB,
                                           Wfu, Wgu, Wcu, bf, bg, bc);
    phase2_kernel<<<NB * 2, 512, smem2>>>(adj, h0, Wfh, Wgh, Wch, out);
    phase3_kernel<<<NB * NT, 128>>>(dW1, db1, dW2, db2, dW3, db3, osc, obi, out);
}